// round 1
// baseline (speedup 1.0000x reference)
#include <cuda_runtime.h>
#include <cuda_bf16.h>

// Involution: B=4, C=256, G=16, K=7, S=1, P=3, R=4, H=W=56
// inputs: x (4,256,56,56) f32 | reduce_w (64,256) | reduce_b (64) | span_w (784,64) | span_b (784)
// out: (4,256,56,56) f32

#define HW 3136   // 56*56

// scratch for h = reduce(x): (B=4, 64, 3136) fp32 = 3.2 MB
__device__ float g_h[4 * 64 * HW];

// ---------------------------------------------------------------------------
// Kernel 1: h[b,o,p] = sum_c x[b,c,p] * reduce_w[o,c] + reduce_b[o]
// GEMM per batch: (64x256) @ (256x3136). Tile: M=64 (full), N=112, K=32 chunks.
// grid (28, 4), block 256. Each thread: 4 o x 7 p accumulators.
// ---------------------------------------------------------------------------
__global__ __launch_bounds__(256) void reduce_kernel(
    const float* __restrict__ x,
    const float* __restrict__ rw,
    const float* __restrict__ rb)
{
    const int b  = blockIdx.y;
    const int n0 = blockIdx.x * 112;
    __shared__ float ws[64 * 32];    // [o][k]
    __shared__ float xs[32 * 112];   // [k][p]

    const int tid = threadIdx.x;
    const int o0 = (tid >> 4) * 4;   // 0..60
    const int p0 = (tid & 15) * 7;   // 0..105

    float acc[4][7];
    #pragma unroll
    for (int i = 0; i < 4; i++)
        #pragma unroll
        for (int j = 0; j < 7; j++) acc[i][j] = 0.f;

    for (int kb = 0; kb < 256; kb += 32) {
        // load reduce_w chunk: 64x32 = 2048
        #pragma unroll
        for (int i = 0; i < 8; i++) {
            int e = tid + i * 256;
            int o = e >> 5, k = e & 31;
            ws[e] = rw[o * 256 + kb + k];
        }
        // load x chunk: 32x112 = 3584
        #pragma unroll
        for (int i = 0; i < 14; i++) {
            int e = tid + i * 256;
            int k = e / 112, p = e - k * 112;
            xs[e] = x[(b * 256 + kb + k) * HW + n0 + p];
        }
        __syncthreads();

        #pragma unroll
        for (int k = 0; k < 32; k++) {
            float wv[4], xv[7];
            #pragma unroll
            for (int i = 0; i < 4; i++) wv[i] = ws[(o0 + i) * 32 + k];
            #pragma unroll
            for (int j = 0; j < 7; j++) xv[j] = xs[k * 112 + p0 + j];
            #pragma unroll
            for (int i = 0; i < 4; i++)
                #pragma unroll
                for (int j = 0; j < 7; j++)
                    acc[i][j] = fmaf(wv[i], xv[j], acc[i][j]);
        }
        __syncthreads();
    }

    #pragma unroll
    for (int i = 0; i < 4; i++) {
        float bias = rb[o0 + i];
        #pragma unroll
        for (int j = 0; j < 7; j++)
            g_h[(b * 64 + o0 + i) * HW + n0 + p0 + j] = acc[i][j] + bias;
    }
}

// ---------------------------------------------------------------------------
// Kernel 2 (fused span + involution apply).
// Block = (row_tile of 4 rows x 56 cols, group g, batch b). grid (14, 16, 4).
// SMEM: span_w slice (49x64), span_b slice, h tile (64x224),
//       x group tile with halo (16ch x 10rows x 62cols, zero-padded).
// 224 active threads, one output pixel each:
//   kern[49] = span_w_g @ h[:,pix] + span_b_g   (registers)
//   out[cg]  = sum_{kh,kw} kern[kh*7+kw] * x[g*16+cg, r+kh-3, c+kw-3]
// ---------------------------------------------------------------------------
__global__ __launch_bounds__(256) void inv_kernel(
    const float* __restrict__ x,
    const float* __restrict__ sw,
    const float* __restrict__ sb,
    float* __restrict__ out)
{
    const int r0 = blockIdx.x * 4;   // first output row of tile
    const int g  = blockIdx.y;
    const int b  = blockIdx.z;

    extern __shared__ float smem[];
    float* ws    = smem;             // 3136 : span_w[g*49 .. g*49+48][0..63]
    float* sbias = ws + 3136;        // 64   : span_b slice (49 used)
    float* hs    = sbias + 64;       // 64*224 : h[c][pix]
    float* xt    = hs + 64 * 224;    // 16*10*62 = 9920 : x halo tile

    const int tid = threadIdx.x;

    // ---- loads ----
    for (int e = tid; e < 49 * 64; e += 256)
        ws[e] = sw[g * 49 * 64 + e];
    if (tid < 49) sbias[tid] = sb[g * 49 + tid];

    for (int e = tid; e < 64 * 224; e += 256) {
        int c = e / 224, p = e - c * 224;
        hs[e] = g_h[(b * 64 + c) * HW + r0 * 56 + p];
    }

    for (int e = tid; e < 16 * 10 * 62; e += 256) {
        int cg  = e / 620;
        int rem = e - cg * 620;
        int rr  = rem / 62, cc = rem - rr * 62;
        int gr = r0 + rr - 3;    // global row
        int gc = cc - 3;         // global col
        float v = 0.f;
        if (gr >= 0 && gr < 56 && gc >= 0 && gc < 56)
            v = x[(b * 256 + g * 16 + cg) * HW + gr * 56 + gc];
        xt[e] = v;
    }
    __syncthreads();

    if (tid < 224) {
        // ---- generate per-pixel 7x7 kernel (49 regs) ----
        float kacc[49];
        #pragma unroll
        for (int kk = 0; kk < 49; kk++) kacc[kk] = sbias[kk];

        #pragma unroll 4
        for (int c0 = 0; c0 < 64; c0 += 4) {
            float hreg[4];
            #pragma unroll
            for (int i = 0; i < 4; i++) hreg[i] = hs[(c0 + i) * 224 + tid];
            #pragma unroll
            for (int kk = 0; kk < 49; kk++) {
                #pragma unroll
                for (int i = 0; i < 4; i++)
                    kacc[kk] = fmaf(ws[kk * 64 + c0 + i], hreg[i], kacc[kk]);
            }
        }

        // ---- apply to the 16 channels of this group ----
        const int lr  = tid / 56;         // local row 0..3
        const int col = tid - lr * 56;    // 0..55
        const int row = r0 + lr;

        #pragma unroll 1
        for (int cg = 0; cg < 16; cg++) {
            const float* xp = &xt[cg * 620 + lr * 62 + col];
            float acc = 0.f;
            #pragma unroll
            for (int kh = 0; kh < 7; kh++) {
                #pragma unroll
                for (int kw = 0; kw < 7; kw++)
                    acc = fmaf(kacc[kh * 7 + kw], xp[kh * 62 + kw], acc);
            }
            out[(b * 256 + g * 16 + cg) * HW + row * 56 + col] = acc;
        }
    }
}

extern "C" void kernel_launch(void* const* d_in, const int* in_sizes, int n_in,
                              void* d_out, int out_size)
{
    const float* x  = (const float*)d_in[0];
    const float* rw = (const float*)d_in[1];
    const float* rb = (const float*)d_in[2];
    const float* sw = (const float*)d_in[3];
    const float* sb = (const float*)d_in[4];
    float* out = (float*)d_out;

    const int smem2 = (3136 + 64 + 64 * 224 + 16 * 10 * 62) * sizeof(float); // ~107 KB
    cudaFuncSetAttribute(inv_kernel, cudaFuncAttributeMaxDynamicSharedMemorySize, smem2);

    reduce_kernel<<<dim3(28, 4), 256>>>(x, rw, rb);
    inv_kernel<<<dim3(14, 16, 4), 256, smem2>>>(x, sw, sb, out);
}

// round 2
// speedup vs baseline: 1.1693x; 1.1693x over previous
#include <cuda_runtime.h>
#include <cuda_bf16.h>

// Involution: B=4, C=256, G=16, K=7, S=1, P=3, R=4, H=W=56
// inputs: x (4,256,56,56) f32 | reduce_w (64,256) | reduce_b (64) | span_w (784,64) | span_b (784)
// out: (4,256,56,56) f32

#define HW 3136   // 56*56

// scratch for h = reduce(x): (B=4, 64, 3136) fp32 = 3.2 MB
__device__ float g_h[4 * 64 * HW];

// ---------------------------------------------------------------------------
// Kernel 1: h[b,o,p] = sum_c x[b,c,p] * reduce_w[o,c] + reduce_b[o]
// ---------------------------------------------------------------------------
__global__ __launch_bounds__(256) void reduce_kernel(
    const float* __restrict__ x,
    const float* __restrict__ rw,
    const float* __restrict__ rb)
{
    const int b  = blockIdx.y;
    const int n0 = blockIdx.x * 112;
    __shared__ float ws[64 * 32];    // [o][k]
    __shared__ float xs[32 * 112];   // [k][p]

    const int tid = threadIdx.x;
    const int o0 = (tid >> 4) * 4;   // 0..60
    const int p0 = (tid & 15) * 7;   // 0..105

    float acc[4][7];
    #pragma unroll
    for (int i = 0; i < 4; i++)
        #pragma unroll
        for (int j = 0; j < 7; j++) acc[i][j] = 0.f;

    for (int kb = 0; kb < 256; kb += 32) {
        #pragma unroll
        for (int i = 0; i < 8; i++) {
            int e = tid + i * 256;
            int o = e >> 5, k = e & 31;
            ws[e] = rw[o * 256 + kb + k];
        }
        #pragma unroll
        for (int i = 0; i < 14; i++) {
            int e = tid + i * 256;
            int k = e / 112, p = e - k * 112;
            xs[e] = x[(b * 256 + kb + k) * HW + n0 + p];
        }
        __syncthreads();

        #pragma unroll
        for (int k = 0; k < 32; k++) {
            float wv[4], xv[7];
            #pragma unroll
            for (int i = 0; i < 4; i++) wv[i] = ws[(o0 + i) * 32 + k];
            #pragma unroll
            for (int j = 0; j < 7; j++) xv[j] = xs[k * 112 + p0 + j];
            #pragma unroll
            for (int i = 0; i < 4; i++)
                #pragma unroll
                for (int j = 0; j < 7; j++)
                    acc[i][j] = fmaf(wv[i], xv[j], acc[i][j]);
        }
        __syncthreads();
    }

    #pragma unroll
    for (int i = 0; i < 4; i++) {
        float bias = rb[o0 + i];
        #pragma unroll
        for (int j = 0; j < 7; j++)
            g_h[(b * 64 + o0 + i) * HW + n0 + p0 + j] = acc[i][j] + bias;
    }
}

// ---------------------------------------------------------------------------
// Kernel 2 (fused span GEMM + involution apply), LDS-minimized.
// Block = 4 rows x 56 cols = 224 pixels, group g, batch b. grid (14,16,4).
// Phase 1: kern[49][224] = ws[49][64] @ hs[64][224] as a register-tiled GEMM
//          (thread tile 7kk x 7pix: 14 LDS per 49 FMAs), staged to smem.
// Phase 2: per-pixel apply over 16 group channels from the x halo tile.
// ---------------------------------------------------------------------------
__global__ __launch_bounds__(256) void inv_kernel(
    const float* __restrict__ x,
    const float* __restrict__ sw,
    const float* __restrict__ sb,
    float* __restrict__ out)
{
    const int r0 = blockIdx.x * 4;   // first output row of tile
    const int g  = blockIdx.y;
    const int b  = blockIdx.z;

    extern __shared__ float smem[];
    float* ws    = smem;                 // 3136  : span_w[g][49][64]
    float* sbias = ws + 3136;            // 64    : span_b slice (49 used)
    float* hs    = sbias + 64;           // 14336 : h[c][224 pix]
    float* kernsm= hs + 64 * 224;        // 10976 : kern[49][224 pix]
    float* xt    = kernsm + 49 * 224;    // 9920  : x halo tile 16ch x 10r x 62c

    const int tid = threadIdx.x;

    // ---- loads (all before one sync; global latency overlapped) ----
    {   // span_w slice: 784 float4
        const float4* swv = (const float4*)(sw + g * 49 * 64);
        float4* wsv = (float4*)ws;
        #pragma unroll
        for (int i = 0; i < 4; i++) {
            int e = tid + i * 256;
            if (e < 784) wsv[e] = swv[e];
        }
    }
    if (tid < 49) sbias[tid] = sb[g * 49 + tid];

    {   // h tile: 3584 float4 (g_h rows are 224 contiguous floats here)
        float4* hsv = (float4*)hs;
        #pragma unroll
        for (int i = 0; i < 14; i++) {
            int e = tid + i * 256;          // float4 index
            int c = e / 56, p4 = e - c * 56;
            hsv[e] = *(const float4*)&g_h[(b * 64 + c) * HW + r0 * 56 + p4 * 4];
        }
    }

    {   // x halo tile: 16ch x 10rows x 62cols, zero-padded
        #pragma unroll
        for (int i = 0; i < 39; i++) {
            int e = tid + i * 256;
            if (e < 16 * 10 * 62) {
                int cg  = e / 620;
                int rem = e - cg * 620;
                int rr  = rem / 62, cc = rem - rr * 62;
                int gr = r0 + rr - 3;
                int gc = cc - 3;
                float v = 0.f;
                if (gr >= 0 && gr < 56 && gc >= 0 && gc < 56)
                    v = x[(b * 256 + g * 16 + cg) * HW + gr * 56 + gc];
                xt[e] = v;
            }
        }
    }
    __syncthreads();

    // ---- Phase 1: GEMM kern = ws @ hs, thread tile 7kk x 7pix ----
    const int pixg = tid & 31;    // 0..31  -> pixels pixg*7 .. pixg*7+6
    const int kkg  = tid >> 5;    // 0..7   (kkg==7 idle)

    if (kkg < 7) {
        float kacc[7][7];
        #pragma unroll
        for (int i = 0; i < 7; i++)
            #pragma unroll
            for (int j = 0; j < 7; j++) kacc[i][j] = 0.f;

        const float* wrow = ws + kkg * 7 * 64;
        const float* hcol = hs + pixg * 7;

        #pragma unroll 4
        for (int c = 0; c < 64; c++) {
            float wv[7], hv[7];
            #pragma unroll
            for (int i = 0; i < 7; i++) wv[i] = wrow[i * 64 + c];   // broadcast
            #pragma unroll
            for (int j = 0; j < 7; j++) hv[j] = hcol[c * 224 + j];  // stride-7, cf-free
            #pragma unroll
            for (int i = 0; i < 7; i++)
                #pragma unroll
                for (int j = 0; j < 7; j++)
                    kacc[i][j] = fmaf(wv[i], hv[j], kacc[i][j]);
        }

        #pragma unroll
        for (int i = 0; i < 7; i++) {
            float bias = sbias[kkg * 7 + i];
            #pragma unroll
            for (int j = 0; j < 7; j++)
                kernsm[(kkg * 7 + i) * 224 + pixg * 7 + j] = kacc[i][j] + bias;
        }
    }
    __syncthreads();

    // ---- Phase 2: apply 7x7 dynamic kernel to 16 group channels ----
    if (tid < 224) {
        float kacc[49];
        #pragma unroll
        for (int kk = 0; kk < 49; kk++) kacc[kk] = kernsm[kk * 224 + tid];

        const int lr  = tid / 56;         // local row 0..3
        const int col = tid - lr * 56;    // 0..55
        const int row = r0 + lr;

        #pragma unroll 1
        for (int cg = 0; cg < 16; cg++) {
            const float* xp = &xt[cg * 620 + lr * 62 + col];
            float acc = 0.f;
            #pragma unroll
            for (int kh = 0; kh < 7; kh++) {
                #pragma unroll
                for (int kw = 0; kw < 7; kw++)
                    acc = fmaf(kacc[kh * 7 + kw], xp[kh * 62 + kw], acc);
            }
            out[(b * 256 + g * 16 + cg) * HW + row * 56 + col] = acc;
        }
    }
}

extern "C" void kernel_launch(void* const* d_in, const int* in_sizes, int n_in,
                              void* d_out, int out_size)
{
    const float* x  = (const float*)d_in[0];
    const float* rw = (const float*)d_in[1];
    const float* rb = (const float*)d_in[2];
    const float* sw = (const float*)d_in[3];
    const float* sb = (const float*)d_in[4];
    float* out = (float*)d_out;

    const int smem2 = (3136 + 64 + 64 * 224 + 49 * 224 + 16 * 10 * 62) * sizeof(float); // ~150 KB
    cudaFuncSetAttribute(inv_kernel, cudaFuncAttributeMaxDynamicSharedMemorySize, smem2);

    reduce_kernel<<<dim3(28, 4), 256>>>(x, rw, rb);
    inv_kernel<<<dim3(14, 16, 4), 256, smem2>>>(x, sw, sb, out);
}

// round 3
// speedup vs baseline: 1.3082x; 1.1188x over previous
#include <cuda_runtime.h>
#include <cuda_bf16.h>

// Involution: B=4, C=256, G=16, K=7, S=1, P=3, H=W=56
#define HW 3136

__device__ float g_h[4 * 64 * HW];   // h = reduce(x): (4,64,3136) fp32

// ---- f32x2 helpers (FFMA2: Blackwell packed fp32 pipe) ----
union F2 { float2 f; unsigned long long u; };
__device__ __forceinline__ unsigned long long pk2(float lo, float hi) {
    F2 t; t.f.x = lo; t.f.y = hi; return t.u;
}
__device__ __forceinline__ unsigned long long ffma2(
    unsigned long long a, unsigned long long b, unsigned long long c) {
    unsigned long long d;
    asm("fma.rn.f32x2 %0, %1, %2, %3;" : "=l"(d) : "l"(a), "l"(b), "l"(c));
    return d;
}
__device__ __forceinline__ unsigned long long add2(
    unsigned long long a, unsigned long long b) {
    unsigned long long d;
    asm("add.rn.f32x2 %0, %1, %2;" : "=l"(d) : "l"(a), "l"(b));
    return d;
}

// ---------------------------------------------------------------------------
// Kernel 1: h[b,o,p] = sum_c x[b,c,p]*rw[o,c] + rb[o]
// 56-wide pixel tiles: grid (56,4)=224 CTAs. block 256 (224 active).
// Thread tile: 4 o  x  2 pixel-pairs (pairs at 2*pg + 28*j), FFMA2.
// ---------------------------------------------------------------------------
__global__ __launch_bounds__(256) void reduce_kernel(
    const float* __restrict__ x,
    const float* __restrict__ rw,
    const float* __restrict__ rb)
{
    const int b  = blockIdx.y;
    const int n0 = blockIdx.x * 56;
    __shared__ float ws[64 * 32];   // [o][k]
    __shared__ float xs[32 * 56];   // [k][p]

    const int tid = threadIdx.x;
    const int og = tid / 14;        // 0..18 (>=16 inactive)
    const int pg = tid % 14;
    const int o0 = og * 4;
    const bool act = (tid < 224);

    unsigned long long acc[4][2];
    #pragma unroll
    for (int i = 0; i < 4; i++)
        #pragma unroll
        for (int j = 0; j < 2; j++) acc[i][j] = 0ull;

    for (int kb = 0; kb < 256; kb += 32) {
        #pragma unroll
        for (int i = 0; i < 8; i++) {
            int e = tid + i * 256;
            int o = e >> 5, k = e & 31;
            ws[e] = rw[o * 256 + kb + k];
        }
        #pragma unroll
        for (int i = 0; i < 7; i++) {
            int e = tid + i * 256;
            int k = e / 56, p = e - k * 56;
            xs[e] = x[(b * 256 + kb + k) * HW + n0 + p];
        }
        __syncthreads();

        if (act) {
            #pragma unroll 4
            for (int k = 0; k < 32; k++) {
                unsigned long long wd[4], hv[2];
                #pragma unroll
                for (int i = 0; i < 4; i++) {
                    float w = ws[(o0 + i) * 32 + k];
                    wd[i] = pk2(w, w);
                }
                #pragma unroll
                for (int j = 0; j < 2; j++) {
                    F2 t; t.f = *(const float2*)&xs[k * 56 + 2 * pg + 28 * j];
                    hv[j] = t.u;
                }
                #pragma unroll
                for (int i = 0; i < 4; i++)
                    #pragma unroll
                    for (int j = 0; j < 2; j++)
                        acc[i][j] = ffma2(wd[i], hv[j], acc[i][j]);
            }
        }
        __syncthreads();
    }

    if (act) {
        #pragma unroll
        for (int i = 0; i < 4; i++) {
            float bias = rb[o0 + i];
            unsigned long long bd = pk2(bias, bias);
            #pragma unroll
            for (int j = 0; j < 2; j++) {
                F2 r; r.u = add2(acc[i][j], bd);
                *(float2*)&g_h[(b * 64 + o0 + i) * HW + n0 + 2 * pg + 28 * j] = r.f;
            }
        }
    }
}

// ---------------------------------------------------------------------------
// Kernel 2 (fused span GEMM + apply). grid (14,16,4), block 256.
// smem 107KB -> 2 CTAs/SM. kern overlays the hs buffer after phase 1.
// Phase 1: 7kk x (4 pixel-pairs at 2*pixg + 56*j), FFMA2, dense LDS.64.
// Phase 2: per-pixel scalar apply over 16 group channels.
// ---------------------------------------------------------------------------
__global__ __launch_bounds__(256, 2) void inv_kernel(
    const float* __restrict__ x,
    const float* __restrict__ sw,
    const float* __restrict__ sb,
    float* __restrict__ out)
{
    const int r0 = blockIdx.x * 4;
    const int g  = blockIdx.y;
    const int b  = blockIdx.z;

    extern __shared__ float smem[];
    float* ws    = smem;             // 3136 : span_w[g][49][64]
    float* sbias = ws + 3136;        // 64
    float* hsk   = sbias + 64;       // 14336 : h[c][224], later kern[49][224]
    float* xt    = hsk + 64 * 224;   // 9920 : x halo 16ch x 10r x 62c

    const int tid = threadIdx.x;

    // ---- stage loads ----
    {
        const float4* swv = (const float4*)(sw + g * 49 * 64);
        float4* wsv = (float4*)ws;
        #pragma unroll
        for (int i = 0; i < 4; i++) {
            int e = tid + i * 256;
            if (e < 784) wsv[e] = swv[e];
        }
    }
    if (tid < 49) sbias[tid] = sb[g * 49 + tid];

    {
        float4* hsv = (float4*)hsk;
        #pragma unroll
        for (int i = 0; i < 14; i++) {
            int e = tid + i * 256;
            int c = e / 56, p4 = e - c * 56;
            hsv[e] = *(const float4*)&g_h[(b * 64 + c) * HW + r0 * 56 + p4 * 4];
        }
    }

    {
        #pragma unroll
        for (int i = 0; i < 39; i++) {
            int e = tid + i * 256;
            if (e < 16 * 10 * 62) {
                int cg  = e / 620;
                int rem = e - cg * 620;
                int rr  = rem / 62, cc = rem - rr * 62;
                int gr = r0 + rr - 3;
                int gc = cc - 3;
                float v = 0.f;
                if (gr >= 0 && gr < 56 && gc >= 0 && gc < 56)
                    v = x[(b * 256 + g * 16 + cg) * HW + gr * 56 + gc];
                xt[e] = v;
            }
        }
    }
    __syncthreads();

    // ---- Phase 1: kern = ws @ hs (FFMA2, 7kk x 8pix as 4 stride-56 pairs) ----
    const int kkg  = tid / 28;       // 0..6 active (7,8 idle)
    const int pixg = tid % 28;

    unsigned long long kacc[7][4];
    #pragma unroll
    for (int i = 0; i < 7; i++)
        #pragma unroll
        for (int j = 0; j < 4; j++) kacc[i][j] = 0ull;

    if (kkg < 7) {
        const float* wrow = ws + kkg * 7 * 64;
        #pragma unroll 4
        for (int c = 0; c < 64; c++) {
            unsigned long long wd[7], hv[4];
            #pragma unroll
            for (int i = 0; i < 7; i++) {
                float w = wrow[i * 64 + c];
                wd[i] = pk2(w, w);
            }
            #pragma unroll
            for (int j = 0; j < 4; j++) {
                F2 t; t.f = *(const float2*)&hsk[c * 224 + 2 * pixg + 56 * j];
                hv[j] = t.u;
            }
            #pragma unroll
            for (int i = 0; i < 7; i++)
                #pragma unroll
                for (int j = 0; j < 4; j++)
                    kacc[i][j] = ffma2(wd[i], hv[j], kacc[i][j]);
        }
    }
    __syncthreads();   // all reads of hs complete before kern overwrite

    if (kkg < 7) {
        #pragma unroll
        for (int i = 0; i < 7; i++) {
            float bias = sbias[kkg * 7 + i];
            unsigned long long bd = pk2(bias, bias);
            #pragma unroll
            for (int j = 0; j < 4; j++) {
                F2 r; r.u = add2(kacc[i][j], bd);
                *(float2*)&hsk[(kkg * 7 + i) * 224 + 2 * pixg + 56 * j] = r.f;
            }
        }
    }
    __syncthreads();

    // ---- Phase 2: apply 7x7 dynamic kernel to 16 group channels ----
    if (tid < 224) {
        float kc[49];
        #pragma unroll
        for (int kk = 0; kk < 49; kk++) kc[kk] = hsk[kk * 224 + tid];

        const int lr  = tid / 56;
        const int col = tid - lr * 56;
        const int row = r0 + lr;

        #pragma unroll 1
        for (int cg = 0; cg < 16; cg++) {
            const float* xp = &xt[cg * 620 + lr * 62 + col];
            float acc = 0.f;
            #pragma unroll
            for (int kh = 0; kh < 7; kh++) {
                #pragma unroll
                for (int kw = 0; kw < 7; kw++)
                    acc = fmaf(kc[kh * 7 + kw], xp[kh * 62 + kw], acc);
            }
            out[(b * 256 + g * 16 + cg) * HW + row * 56 + col] = acc;
        }
    }
}

extern "C" void kernel_launch(void* const* d_in, const int* in_sizes, int n_in,
                              void* d_out, int out_size)
{
    const float* x  = (const float*)d_in[0];
    const float* rw = (const float*)d_in[1];
    const float* rb = (const float*)d_in[2];
    const float* sw = (const float*)d_in[3];
    const float* sb = (const float*)d_in[4];
    float* out = (float*)d_out;

    const int smem2 = (3136 + 64 + 64 * 224 + 16 * 10 * 62) * sizeof(float); // ~107 KB
    cudaFuncSetAttribute(inv_kernel, cudaFuncAttributeMaxDynamicSharedMemorySize, smem2);

    reduce_kernel<<<dim3(56, 4), 256>>>(x, rw, rb);
    inv_kernel<<<dim3(14, 16, 4), 256, smem2>>>(x, sw, sb, out);
}